// round 3
// baseline (speedup 1.0000x reference)
#include <cuda_runtime.h>

// FKPositionLoss: B=256, J=24, T=1024, F=8 sampled frames.
// Loss = mean over (B,F,J,3) of (pred_pos - target_pos)^2.
// Root translation is an identical additive term on both sides -> cancels in the MSE.

#define NB 256
#define NJ 24
#define NT 1024
#define NF 8
#define NITEMS (NB * NF)      // 2048 (b,f) items
#define IPB 2                 // items per block
#define NTHREADS 96           // IPB * 2 sides * 24 joints
#define NGRID (NITEMS / IPB)  // 1024 blocks
#define DENOM 147456.0        // B*F*J*3

// Self-resetting cross-block accumulator (zero at module load, reset by the
// final block each launch -> deterministic under CUDA-graph replay).
__device__ double g_sum;
__device__ unsigned int g_count;

// jnp.linspace(0, 1023, 8).astype(int32)
__constant__ int c_tidx[NF] = {0, 146, 292, 438, 584, 730, 876, 1023};

__global__ __launch_bounds__(NTHREADS) void fk_loss_kernel(
    const float* __restrict__ pred,
    const float* __restrict__ targ,
    const float* __restrict__ offsets,
    float* __restrict__ out)
{
    __shared__ float4 qsh[IPB][2][NJ];      // local quats (w,x,y,z)
    __shared__ float  psh[IPB][2][NJ][3];   // joint positions, both sides
    __shared__ float  offs[NJ * 3];
    __shared__ float  wsum[3];              // per-warp partials

    const int tid = threadIdx.x;

    if (tid < NJ * 3) offs[tid] = offsets[tid];

    // ---------------- phase 1: gather 6d, convert to quaternion ----------------
    // One thread per (item, side, joint): 6 independent strided loads (max MLP).
    {
        const int item_l = tid / 48;
        const int r      = tid - item_l * 48;
        const int side   = r / NJ;
        const int j      = r - side * NJ;
        const int item   = blockIdx.x * IPB + item_l;
        const int b      = item >> 3;
        const int f      = item & 7;

        const float* __restrict__ src = side ? targ : pred;
        const long base = ((long)(b * NJ + j) * 6) * NT + c_tidx[f];

        const float r0 = __ldg(src + base + 0 * NT);
        const float r1 = __ldg(src + base + 1 * NT);
        const float r2 = __ldg(src + base + 2 * NT);
        const float r3 = __ldg(src + base + 3 * NT);
        const float r4 = __ldg(src + base + 4 * NT);
        const float r5 = __ldg(src + base + 5 * NT);

        // Gram-Schmidt (Zhou et al.): rows b1, b2, b3 = b1 x b2
        const float n1   = sqrtf(r0 * r0 + r1 * r1 + r2 * r2);
        const float inv1 = 1.0f / fmaxf(n1, 1e-8f);
        const float b1x = r0 * inv1, b1y = r1 * inv1, b1z = r2 * inv1;

        const float d  = b1x * r3 + b1y * r4 + b1z * r5;
        const float ux = r3 - d * b1x, uy = r4 - d * b1y, uz = r5 - d * b1z;
        const float n2   = sqrtf(ux * ux + uy * uy + uz * uz);
        const float inv2 = 1.0f / fmaxf(n2, 1e-8f);
        const float b2x = ux * inv2, b2y = uy * inv2, b2z = uz * inv2;

        const float b3x = b1y * b2z - b1z * b2y;
        const float b3y = b1z * b2x - b1x * b2z;
        const float b3z = b1x * b2y - b1y * b2x;

        const float m00 = b1x, m01 = b1y, m02 = b1z;
        const float m10 = b2x, m11 = b2y, m12 = b2z;
        const float m20 = b3x, m21 = b3y, m22 = b3z;

        // matrix -> quaternion (pytorch3d-style; argmax candidate, lowest index
        // wins ties, matching jnp.argmax)
        const float q0 = sqrtf(fmaxf(1.0f + m00 + m11 + m22, 0.0f));
        const float q1 = sqrtf(fmaxf(1.0f + m00 - m11 - m22, 0.0f));
        const float q2 = sqrtf(fmaxf(1.0f - m00 + m11 - m22, 0.0f));
        const float q3 = sqrtf(fmaxf(1.0f - m00 - m11 + m22, 0.0f));

        int best = 0; float bq = q0;
        if (q1 > bq) { bq = q1; best = 1; }
        if (q2 > bq) { bq = q2; best = 2; }
        if (q3 > bq) { bq = q3; best = 3; }
        const float s = 0.5f / fmaxf(bq, 0.1f);

        float qw, qx, qy, qz;
        if (best == 0)      { qw = q0 * q0;  qx = m21 - m12; qy = m02 - m20; qz = m10 - m01; }
        else if (best == 1) { qw = m21 - m12; qx = q1 * q1;  qy = m10 + m01; qz = m02 + m20; }
        else if (best == 2) { qw = m02 - m20; qx = m10 + m01; qy = q2 * q2;  qz = m12 + m21; }
        else                { qw = m10 - m01; qx = m20 + m02; qy = m21 + m12; qz = q3 * q3;  }

        qsh[item_l][side][j] = make_float4(qw * s, qx * s, qy * s, qz * s);
    }
    __syncthreads();

    // ---------------- phase 2: forward kinematics (4 threads/block) ----------------
    // Fully unrolled 24-joint chain, register-resident (no STS/LDS on the
    // dependency path; registers die at the final shared write).
    if (tid < IPB * 2) {
        const int fk_item = tid >> 1;
        const int fk_side = tid & 1;

        float gw[NJ], gx[NJ], gy[NJ], gz[NJ];
        float px[NJ], py[NJ], pz[NJ];
        const int par[NJ] = {-1, 0, 0, 0, 1, 2, 3, 4, 5, 6, 7, 8,
                              9, 9, 9, 12, 13, 14, 16, 17, 18, 19, 20, 21};
#pragma unroll
        for (int j = 0; j < NJ; j++) {
            const float4 lq = qsh[fk_item][fk_side][j];
            if (par[j] < 0) {
                gw[j] = lq.x; gx[j] = lq.y; gy[j] = lq.z; gz[j] = lq.w;
                px[j] = 0.0f; py[j] = 0.0f; pz[j] = 0.0f;  // root translation cancels
            } else {
                const int p = par[j];
                const float w1 = gw[p], x1 = gx[p], y1 = gy[p], z1 = gz[p];
                const float w2 = lq.x, x2 = lq.y, y2 = lq.z, z2 = lq.w;
                gw[j] = w1 * w2 - x1 * x2 - y1 * y2 - z1 * z2;
                gx[j] = w1 * x2 + x1 * w2 + y1 * z2 - z1 * y2;
                gy[j] = w1 * y2 - x1 * z2 + y1 * w2 + z1 * x2;
                gz[j] = w1 * z2 + x1 * y2 - y1 * x2 + z1 * w2;

                const float vx = offs[j * 3 + 0];
                const float vy = offs[j * 3 + 1];
                const float vz = offs[j * 3 + 2];
                const float tx = 2.0f * (y1 * vz - z1 * vy);
                const float ty = 2.0f * (z1 * vx - x1 * vz);
                const float tz = 2.0f * (x1 * vy - y1 * vx);
                px[j] = px[p] + vx + w1 * tx + (y1 * tz - z1 * ty);
                py[j] = py[p] + vy + w1 * ty + (z1 * tx - x1 * tz);
                pz[j] = pz[p] + vz + w1 * tz + (x1 * ty - y1 * tx);
            }
        }
#pragma unroll
        for (int j = 0; j < NJ; j++) {
            psh[fk_item][fk_side][j][0] = px[j];
            psh[fk_item][fk_side][j][1] = py[j];
            psh[fk_item][fk_side][j][2] = pz[j];
        }
    }
    __syncthreads();

    // ---------------- phase 3: squared diff, block reduce, global atomic ----------
    {
        // 144 scalar diff terms (IPB*NJ*3) over 96 threads.
        const float* p0 = &psh[0][0][0][0];   // layout [item][side][joint][xyz]
        float acc = 0.0f;
#pragma unroll
        for (int e = tid; e < IPB * NJ * 3; e += NTHREADS) {
            const int item = e / (NJ * 3);
            const int rem  = e - item * (NJ * 3);
            const float a = p0[(item * 2 + 0) * (NJ * 3) + rem];
            const float b = p0[(item * 2 + 1) * (NJ * 3) + rem];
            const float dd = a - b;
            acc += dd * dd;
        }
#pragma unroll
        for (int off = 16; off > 0; off >>= 1)
            acc += __shfl_down_sync(0xffffffffu, acc, off);
        if ((tid & 31) == 0) wsum[tid >> 5] = acc;
    }
    __syncthreads();

    if (tid == 0) {
        const double blocksum = (double)wsum[0] + (double)wsum[1] + (double)wsum[2];
        atomicAdd(&g_sum, blocksum);
        __threadfence();
        const unsigned int old = atomicAdd(&g_count, 1u);
        if (old == NGRID - 1) {
            const double tot = atomicAdd(&g_sum, 0.0);  // atomic read after all adds
            out[0] = (float)(tot / DENOM);
            g_sum = 0.0;            // reset for next graph replay
            __threadfence();
            g_count = 0u;
        }
    }
}

extern "C" void kernel_launch(void* const* d_in, const int* in_sizes, int n_in,
                              void* d_out, int out_size)
{
    // Inputs (metadata order): pred_rot_6d, target_rot_6d, root_translation, offsets.
    // Selected defensively by element count; root_translation unused (cancels in MSE).
    const float* pred = nullptr;
    const float* targ = nullptr;
    const float* offsets = nullptr;
    const int big = NB * NJ * 6 * NT;  // 37,748,736
    for (int i = 0; i < n_in; i++) {
        if (in_sizes[i] == big) {
            if (!pred) pred = (const float*)d_in[i];
            else if (!targ) targ = (const float*)d_in[i];
        } else if (in_sizes[i] == NJ * 3) {
            offsets = (const float*)d_in[i];
        }
    }
    fk_loss_kernel<<<NGRID, NTHREADS>>>(pred, targ, offsets, (float*)d_out);
}